// round 2
// baseline (speedup 1.0000x reference)
#include <cuda_runtime.h>
#include <math.h>

// ---------------- problem dims ----------------
#define NB 8
#define TT 2048
#define DD 1024
#define HH 1536
#define GG 3072              // 2*H
#define MM (NB*TT)           // 16384
#define NCHUNK 16
#define CLEN (TT/NCHUNK)     // 128

// ---------------- scratch (static device globals; allocation-free) ----------------
__device__ float g_u[(size_t)MM*GG];       // u = x @ W_in^T   [M, 2H]  (gate | xh)
__device__ float g_xc[(size_t)MM*HH];      // conv output      [M, H]
__device__ float g_g[(size_t)MM*GG];       // gates GEMM out -> later (alpha | xs) in place
__device__ float g_h[(size_t)MM*HH];       // local scan h
__device__ float g_cumA[(size_t)MM*HH];    // cumulative alpha within chunk
__device__ float g_ga[(size_t)MM*HH];      // gelu(gate) * h
__device__ float g_carryA[NB*NCHUNK*HH];
__device__ float g_carryH[NB*NCHUNK*HH];
__device__ float g_chunkIn[NB*NCHUNK*HH];

// ---------------- fp32 SGEMM body: C[.,N] = A[.,K] * B[N,K]^T (+bias[N]) --------
// block tile 128x128, BK=8, 256 threads, 8x8 per thread, double-buffered smem
__device__ __forceinline__ void sgemm_body(
    const float* __restrict__ A, const float* __restrict__ B,
    const float* __restrict__ bias, float* __restrict__ C,
    int Ndim, int Kdim)
{
    __shared__ float As[2][8][128];
    __shared__ float Bs[2][8][128];

    const int tid = threadIdx.x;
    const int tx = tid & 15;        // 0..15 -> N direction
    const int ty = tid >> 4;        // 0..15 -> M direction
    const int m0 = blockIdx.y * 128;
    const int n0 = blockIdx.x * 128;

    // global->smem loader mapping: one float4 per thread per operand
    const int lrow = tid >> 1;            // 0..127
    const int lk   = (tid & 1) * 4;       // 0 or 4

    const float* Ag = A + (size_t)(m0 + lrow) * Kdim + lk;
    const float* Bg = B + (size_t)(n0 + lrow) * Kdim + lk;

    float acc[8][8];
#pragma unroll
    for (int i = 0; i < 8; i++)
#pragma unroll
        for (int j = 0; j < 8; j++) acc[i][j] = 0.f;

    // prologue: load tile 0 into buffer 0
    {
        float4 av = *(const float4*)(Ag);
        float4 bv = *(const float4*)(Bg);
        As[0][lk + 0][lrow] = av.x; As[0][lk + 1][lrow] = av.y;
        As[0][lk + 2][lrow] = av.z; As[0][lk + 3][lrow] = av.w;
        Bs[0][lk + 0][lrow] = bv.x; Bs[0][lk + 1][lrow] = bv.y;
        Bs[0][lk + 2][lrow] = bv.z; Bs[0][lk + 3][lrow] = bv.w;
    }
    __syncthreads();

    const int nsteps = Kdim / 8;
    for (int s = 0; s < nsteps; s++) {
        const int cur = s & 1;
        float4 av, bv;
        const bool more = (s + 1 < nsteps);
        if (more) {
            av = *(const float4*)(Ag + (s + 1) * 8);
            bv = *(const float4*)(Bg + (s + 1) * 8);
        }

#pragma unroll
        for (int k = 0; k < 8; k++) {
            float a[8], b[8];
            *(float4*)(a)     = *(const float4*)&As[cur][k][ty * 8];
            *(float4*)(a + 4) = *(const float4*)&As[cur][k][ty * 8 + 4];
            *(float4*)(b)     = *(const float4*)&Bs[cur][k][tx * 8];
            *(float4*)(b + 4) = *(const float4*)&Bs[cur][k][tx * 8 + 4];
#pragma unroll
            for (int i = 0; i < 8; i++)
#pragma unroll
                for (int j = 0; j < 8; j++)
                    acc[i][j] += a[i] * b[j];
        }

        if (more) {
            const int nxt = cur ^ 1;
            As[nxt][lk + 0][lrow] = av.x; As[nxt][lk + 1][lrow] = av.y;
            As[nxt][lk + 2][lrow] = av.z; As[nxt][lk + 3][lrow] = av.w;
            Bs[nxt][lk + 0][lrow] = bv.x; Bs[nxt][lk + 1][lrow] = bv.y;
            Bs[nxt][lk + 2][lrow] = bv.z; Bs[nxt][lk + 3][lrow] = bv.w;
            __syncthreads();
        }
    }

    float bj[8];
#pragma unroll
    for (int j = 0; j < 8; j++)
        bj[j] = bias ? bias[n0 + tx * 8 + j] : 0.f;

#pragma unroll
    for (int i = 0; i < 8; i++) {
        float* Cp = C + (size_t)(m0 + ty * 8 + i) * Ndim + n0 + tx * 8;
        float4 v0, v1;
        v0.x = acc[i][0] + bj[0]; v0.y = acc[i][1] + bj[1];
        v0.z = acc[i][2] + bj[2]; v0.w = acc[i][3] + bj[3];
        v1.x = acc[i][4] + bj[4]; v1.y = acc[i][5] + bj[5];
        v1.z = acc[i][6] + bj[6]; v1.w = acc[i][7] + bj[7];
        *(float4*)(Cp)     = v0;
        *(float4*)(Cp + 4) = v1;
    }
}

// ---- thin wrappers binding scratch globals (no cudaGetSymbolAddress needed) ----
__global__ __launch_bounds__(256) void sgemm_in(const float* __restrict__ x,
                                               const float* __restrict__ W_in)
{
    sgemm_body(x, W_in, nullptr, g_u, GG, DD);
}
__global__ __launch_bounds__(256) void sgemm_gates(const float* __restrict__ W_gates,
                                                   const float* __restrict__ b_gates)
{
    sgemm_body(g_xc, W_gates, b_gates, g_g, GG, HH);
}
__global__ __launch_bounds__(256) void sgemm_out(const float* __restrict__ W_out,
                                                 float* __restrict__ out)
{
    sgemm_body(g_ga, W_out, nullptr, out, DD, HH);
}

// ---------------- causal depthwise conv (K=4) on xh half of u ----------------
__global__ __launch_bounds__(256) void conv_kernel(
    const float* __restrict__ cw, const float* __restrict__ cb)
{
    int id = blockIdx.x * blockDim.x + threadIdx.x;
    if (id >= MM * HH) return;
    int h = id % HH;
    int m = id / HH;
    int t = m % TT;
    int mbase = m - t;                       // n*T
    float acc = cb[h];
#pragma unroll
    for (int k = 0; k < 4; k++) {
        int tt = t + k - 3;
        if (tt >= 0)
            acc += cw[h * 4 + k] * g_u[(size_t)(mbase + tt) * GG + HH + h];
    }
    g_xc[id] = acc;
}

// ---------------- gating math: g_g -> (alpha | xs) in place ----------------
__global__ __launch_bounds__(256) void gate_kernel(const float* __restrict__ fb)
{
    int id = blockIdx.x * blockDim.x + threadIdx.x;
    if (id >= MM * HH) return;
    int h = id % HH;
    int m = id / HH;
    size_t base = (size_t)m * GG;
    float f  = g_g[base + h];
    float iv = g_g[base + HH + h];
    float sp = log1pf(expf(fb[h]));                 // softplus(forget_base)
    float sf = 1.f / (1.f + expf(-f));              // sigmoid(forget)
    float la = -8.f * sp * sf;
    float alpha = expf(la);
    float beta  = sqrtf(1.f - alpha * alpha + 1e-6f);
    float si = 1.f / (1.f + expf(-iv));             // sigmoid(inp)
    float xs = beta * si * g_xc[id];
    g_g[base + h]      = alpha;
    g_g[base + HH + h] = xs;
}

// ---------------- scan pass 1: per-chunk local scan + cumprod(alpha) ----------------
__global__ __launch_bounds__(256) void scan1_kernel()
{
    int id = blockIdx.x * blockDim.x + threadIdx.x;
    if (id >= NB * NCHUNK * HH) return;
    int h = id % HH;
    int r = id / HH;
    int c = r % NCHUNK;
    int n = r / NCHUNK;
    float arun = 1.f, hrun = 0.f;
    int t0 = c * CLEN;
    for (int tl = 0; tl < CLEN; tl++) {
        size_t m = (size_t)n * TT + t0 + tl;
        float a = g_g[m * GG + h];
        float x = g_g[m * GG + HH + h];
        hrun = a * hrun + x;
        arun *= a;
        g_h[m * HH + h]    = hrun;
        g_cumA[m * HH + h] = arun;
    }
    g_carryA[id] = arun;   // id == (n*NCHUNK + c)*HH + h
    g_carryH[id] = hrun;
}

// ---------------- scan pass 2: combine chunk carries serially (tiny) ----------------
__global__ __launch_bounds__(256) void scan2_kernel()
{
    int id = blockIdx.x * blockDim.x + threadIdx.x;
    if (id >= NB * HH) return;
    int h = id % HH;
    int n = id / HH;
    float hin = 0.f;
    for (int c = 0; c < NCHUNK; c++) {
        int j = (n * NCHUNK + c) * HH + h;
        g_chunkIn[j] = hin;
        hin = g_carryA[j] * hin + g_carryH[j];
    }
}

// ---------------- scan fixup + gelu(gate)*h fused ----------------
__global__ __launch_bounds__(256) void mul_kernel()
{
    int id = blockIdx.x * blockDim.x + threadIdx.x;
    if (id >= MM * HH) return;
    int h = id % HH;
    int m = id / HH;
    int t = m % TT;
    int n = m / TT;
    int c = t / CLEN;
    float hv = g_h[id] + g_cumA[id] * g_chunkIn[(n * NCHUNK + c) * HH + h];
    float gate = g_u[(size_t)m * GG + h];
    float ge = 0.5f * gate * (1.f + erff(gate * 0.70710678118654752f));
    g_ga[id] = ge * hv;
}

// ---------------- launch ----------------
extern "C" void kernel_launch(void* const* d_in, const int* in_sizes, int n_in,
                              void* d_out, int out_size)
{
    const float* x          = (const float*)d_in[0];
    const float* W_in       = (const float*)d_in[1];
    const float* conv_w     = (const float*)d_in[2];
    const float* conv_b     = (const float*)d_in[3];
    const float* W_gates    = (const float*)d_in[4];
    const float* b_gates    = (const float*)d_in[5];
    const float* forget_b   = (const float*)d_in[6];
    const float* W_out      = (const float*)d_in[7];
    float* out = (float*)d_out;

    // 1) u = x @ W_in^T        [16384,1024] x [3072,1024]^T
    {
        dim3 grid(GG / 128, MM / 128);
        sgemm_in<<<grid, 256>>>(x, W_in);
    }
    // 2) causal depthwise conv on xh half
    conv_kernel<<<(MM * HH) / 256, 256>>>(conv_w, conv_b);
    // 3) g = xc @ W_gates^T + b_gates
    {
        dim3 grid(GG / 128, MM / 128);
        sgemm_gates<<<grid, 256>>>(W_gates, b_gates);
    }
    // 4) gating -> alpha, xs
    gate_kernel<<<(MM * HH) / 256, 256>>>(forget_b);
    // 5) chunked linear scan
    scan1_kernel<<<(NB * NCHUNK * HH) / 256, 256>>>();
    scan2_kernel<<<(NB * HH + 255) / 256, 256>>>();
    // 6) fixup + gelu(gate)*h
    mul_kernel<<<(MM * HH) / 256, 256>>>();
    // 7) out = ga @ W_out^T
    {
        dim3 grid(DD / 128, MM / 128);
        sgemm_out<<<grid, 256>>>(W_out, out);
    }
}

// round 4
// speedup vs baseline: 2.0364x; 2.0364x over previous
#include <cuda_runtime.h>
#include <cuda_bf16.h>
#include <math.h>
#include <stdint.h>

// ---------------- problem dims ----------------
#define NB 8
#define TT 2048
#define DD 1024
#define HH 1536
#define GG 3072              // 2*H
#define MM (NB*TT)           // 16384
#define NCHUNK 16
#define CLEN (TT/NCHUNK)     // 128

// ---------------- scratch ----------------
__device__ float g_u[(size_t)MM*GG];        // u = x @ W_in^T  (gate | xh)
__device__ float g_xc[(size_t)MM*HH];       // conv output fp32
__device__ float g_g[(size_t)MM*GG];        // gates GEMM out -> (alpha | xs) in place
__device__ float g_h[(size_t)MM*HH];
__device__ float g_cumA[(size_t)MM*HH];
__device__ float g_carryA[NB*NCHUNK*HH];
__device__ float g_carryH[NB*NCHUNK*HH];
__device__ float g_chunkIn[NB*NCHUNK*HH];
// split-bf16 operand buffers (A reused for x / xc / ga; B reused for the 3 weights)
__device__ __nv_bfloat16 g_ahi[(size_t)MM*HH];
__device__ __nv_bfloat16 g_alo[(size_t)MM*HH];
__device__ __nv_bfloat16 g_bhi[(size_t)GG*HH];
__device__ __nv_bfloat16 g_blo[(size_t)GG*HH];

// ---------------- PTX helpers (baseline ISA only: ldmatrix + mma.sync) ----------
__device__ __forceinline__ uint32_t smem_u32(const void* p) {
    uint32_t a;
    asm("{ .reg .u64 t; cvta.to.shared.u64 t, %1; cvt.u32.u64 %0, t; }" : "=r"(a) : "l"(p));
    return a;
}
__device__ __forceinline__ void ldsm_x4(uint32_t& r0, uint32_t& r1, uint32_t& r2, uint32_t& r3,
                                        uint32_t addr) {
    asm volatile("ldmatrix.sync.aligned.m8n8.x4.shared.b16 {%0,%1,%2,%3}, [%4];"
                 : "=r"(r0), "=r"(r1), "=r"(r2), "=r"(r3) : "r"(addr));
}
__device__ __forceinline__ void mma16816(float* c,
                                         uint32_t a0, uint32_t a1, uint32_t a2, uint32_t a3,
                                         uint32_t b0, uint32_t b1) {
    asm volatile(
        "mma.sync.aligned.m16n8k16.row.col.f32.bf16.bf16.f32 "
        "{%0,%1,%2,%3}, {%4,%5,%6,%7}, {%8,%9}, {%0,%1,%2,%3};"
        : "+f"(c[0]), "+f"(c[1]), "+f"(c[2]), "+f"(c[3])
        : "r"(a0), "r"(a1), "r"(a2), "r"(a3), "r"(b0), "r"(b1));
}

// ---------------- split-bf16 TN GEMM via mma.sync ----------------
// C[M,N] = (Ahi+Alo)[M,K] * (Bhi+Blo)[N,K]^T (+bias); 3 terms: hi*hi + hi*lo + lo*hi
// block 128x128, BK=32, 256 threads = 8 warps (2 M x 4 N), warp tile 64x32
#define BM 128
#define BN 128
#define BK 32
#define SSTR 40     // smem row stride in bf16 elements (32 + 8 pad)

__device__ __forceinline__ void tn_gemm_body(
    const __nv_bfloat16* __restrict__ Ahi, const __nv_bfloat16* __restrict__ Alo,
    const __nv_bfloat16* __restrict__ Bhi, const __nv_bfloat16* __restrict__ Blo,
    const float* __restrict__ bias, float* __restrict__ C,
    int Ndim, int Kdim)
{
    __shared__ __align__(16) __nv_bfloat16 sA[BM * SSTR];
    __shared__ __align__(16) __nv_bfloat16 sB[BN * SSTR];

    const int tid = threadIdx.x;
    const int wid = tid >> 5;
    const int lane = tid & 31;
    const int warp_m = wid >> 2;       // 0..1
    const int warp_n = wid & 3;        // 0..3
    const int m0 = blockIdx.y * BM;
    const int n0 = blockIdx.x * BN;

    const uint32_t sAu = smem_u32(sA);
    const uint32_t sBu = smem_u32(sB);

    // loader: 512 uint4 per tile, 256 threads -> indices tid and tid+256
    const int r0i = tid >> 2,  q0 = tid & 3;          // i = tid
    const int r1i = (tid + 256) >> 2, q1 = tid & 3;   // i = tid+256 (q same: (i&3)==(tid&3))

    float acc[4][4][4];
#pragma unroll
    for (int i = 0; i < 4; i++)
#pragma unroll
        for (int j = 0; j < 4; j++)
#pragma unroll
            for (int v = 0; v < 4; v++) acc[i][j][v] = 0.f;

    const int kcs = Kdim / BK;
    const int nch = 3 * kcs;

    uint4 ra0, ra1, rb0, rb1;

    // ---- fetch chunk ch into registers ----
    auto fetch = [&](int ch) {
        const int seg = ch / kcs;
        const int kc  = ch - seg * kcs;
        const __nv_bfloat16* Ap = (seg < 2) ? Ahi : Alo;
        const __nv_bfloat16* Bp = (seg == 1) ? Blo : Bhi;
        const __nv_bfloat16* abase = Ap + (size_t)m0 * Kdim + kc * BK;
        const __nv_bfloat16* bbase = Bp + (size_t)n0 * Kdim + kc * BK;
        ra0 = *(const uint4*)(abase + (size_t)r0i * Kdim + q0 * 8);
        ra1 = *(const uint4*)(abase + (size_t)r1i * Kdim + q1 * 8);
        rb0 = *(const uint4*)(bbase + (size_t)r0i * Kdim + q0 * 8);
        rb1 = *(const uint4*)(bbase + (size_t)r1i * Kdim + q1 * 8);
    };
    auto stage = [&]() {
        *(uint4*)(sA + r0i * SSTR + q0 * 8) = ra0;
        *(uint4*)(sA + r1i * SSTR + q1 * 8) = ra1;
        *(uint4*)(sB + r0i * SSTR + q0 * 8) = rb0;
        *(uint4*)(sB + r1i * SSTR + q1 * 8) = rb1;
    };

    fetch(0);
    stage();
    __syncthreads();

    for (int ch = 0; ch < nch; ch++) {
        const bool more = (ch + 1 < nch);
        if (more) fetch(ch + 1);

        // compute on current smem tiles: 2 k16 steps
#pragma unroll
        for (int kk = 0; kk < 2; kk++) {
            uint32_t a[4][4];
#pragma unroll
            for (int mi = 0; mi < 4; mi++) {
                uint32_t addr = sAu +
                    (uint32_t)(((warp_m * 64 + mi * 16 + (lane & 15)) * SSTR
                                + kk * 16 + (lane >> 4) * 8) * 2);
                ldsm_x4(a[mi][0], a[mi][1], a[mi][2], a[mi][3], addr);
            }
            uint32_t br[2][4];
#pragma unroll
            for (int nb = 0; nb < 2; nb++) {
                uint32_t addr = sBu +
                    (uint32_t)(((warp_n * 32 + nb * 16 + (lane & 15)) * SSTR
                                + kk * 16 + (lane >> 4) * 8) * 2);
                ldsm_x4(br[nb][0], br[nb][1], br[nb][2], br[nb][3], addr);
            }
            // b fragment for n8 tile (nb,sub): sub=0 -> {r0,r2}, sub=1 -> {r1,r3}
#pragma unroll
            for (int mi = 0; mi < 4; mi++) {
#pragma unroll
                for (int nb = 0; nb < 2; nb++) {
                    mma16816(acc[mi][nb * 2 + 0], a[mi][0], a[mi][1], a[mi][2], a[mi][3],
                             br[nb][0], br[nb][2]);
                    mma16816(acc[mi][nb * 2 + 1], a[mi][0], a[mi][1], a[mi][2], a[mi][3],
                             br[nb][1], br[nb][3]);
                }
            }
        }

        __syncthreads();
        if (more) {
            stage();
            __syncthreads();
        }
    }

    // ---- epilogue: write accumulators ----
    const int crow0 = m0 + warp_m * 64 + (lane >> 2);
    const int ccol0 = n0 + warp_n * 32 + (lane & 3) * 2;
#pragma unroll
    for (int mi = 0; mi < 4; mi++) {
#pragma unroll
        for (int ni = 0; ni < 4; ni++) {
            int row = crow0 + mi * 16;
            int col = ccol0 + ni * 8;
            float b0 = 0.f, b1 = 0.f;
            if (bias) { b0 = bias[col]; b1 = bias[col + 1]; }
            float2 v0, v1;
            v0.x = acc[mi][ni][0] + b0; v0.y = acc[mi][ni][1] + b1;
            v1.x = acc[mi][ni][2] + b0; v1.y = acc[mi][ni][3] + b1;
            *(float2*)(C + (size_t)row * Ndim + col)       = v0;
            *(float2*)(C + (size_t)(row + 8) * Ndim + col) = v1;
        }
    }
}

__global__ __launch_bounds__(256) void tcgemm_in()
{
    tn_gemm_body(g_ahi, g_alo, g_bhi, g_blo, nullptr, g_u, GG, DD);
}
__global__ __launch_bounds__(256) void tcgemm_gates(const float* __restrict__ b_gates)
{
    tn_gemm_body(g_ahi, g_alo, g_bhi, g_blo, b_gates, g_g, GG, HH);
}
__global__ __launch_bounds__(256) void tcgemm_out(float* __restrict__ out)
{
    tn_gemm_body(g_ahi, g_alo, g_bhi, g_blo, nullptr, out, DD, HH);
}

// ---------------- fp32 -> (hi, lo) bf16 split ----------------
__device__ __forceinline__ void split1(float v, __nv_bfloat16& hi, __nv_bfloat16& lo) {
    __nv_bfloat16 h = __float2bfloat16(v);
    hi = h;
    lo = __float2bfloat16(v - __bfloat162float(h));
}
__global__ __launch_bounds__(256) void split_x(const float* __restrict__ x, int n4)
{
    int id = blockIdx.x * blockDim.x + threadIdx.x;
    if (id >= n4) return;
    float4 v = ((const float4*)x)[id];
    __nv_bfloat16 h0, h1, h2, h3, l0, l1, l2, l3;
    split1(v.x, h0, l0); split1(v.y, h1, l1);
    split1(v.z, h2, l2); split1(v.w, h3, l3);
    ((__nv_bfloat162*)g_ahi)[id * 2 + 0] = __nv_bfloat162(h0, h1);
    ((__nv_bfloat162*)g_ahi)[id * 2 + 1] = __nv_bfloat162(h2, h3);
    ((__nv_bfloat162*)g_alo)[id * 2 + 0] = __nv_bfloat162(l0, l1);
    ((__nv_bfloat162*)g_alo)[id * 2 + 1] = __nv_bfloat162(l2, l3);
}
__global__ __launch_bounds__(256) void split_w(const float* __restrict__ w, int n4)
{
    int id = blockIdx.x * blockDim.x + threadIdx.x;
    if (id >= n4) return;
    float4 v = ((const float4*)w)[id];
    __nv_bfloat16 h0, h1, h2, h3, l0, l1, l2, l3;
    split1(v.x, h0, l0); split1(v.y, h1, l1);
    split1(v.z, h2, l2); split1(v.w, h3, l3);
    ((__nv_bfloat162*)g_bhi)[id * 2 + 0] = __nv_bfloat162(h0, h1);
    ((__nv_bfloat162*)g_bhi)[id * 2 + 1] = __nv_bfloat162(h2, h3);
    ((__nv_bfloat162*)g_blo)[id * 2 + 0] = __nv_bfloat162(l0, l1);
    ((__nv_bfloat162*)g_blo)[id * 2 + 1] = __nv_bfloat162(l2, l3);
}

// ---------------- causal depthwise conv, fused with split ----------------
__global__ __launch_bounds__(256) void conv_kernel(
    const float* __restrict__ cw, const float* __restrict__ cb)
{
    int id = blockIdx.x * blockDim.x + threadIdx.x;
    if (id >= MM * HH) return;
    int h = id % HH;
    int m = id / HH;
    int t = m % TT;
    int mbase = m - t;
    float acc = cb[h];
#pragma unroll
    for (int k = 0; k < 4; k++) {
        int tt = t + k - 3;
        if (tt >= 0)
            acc += cw[h * 4 + k] * g_u[(size_t)(mbase + tt) * GG + HH + h];
    }
    g_xc[id] = acc;
    __nv_bfloat16 hi, lo;
    split1(acc, hi, lo);
    g_ahi[id] = hi;
    g_alo[id] = lo;
}

// ---------------- gating math ----------------
__global__ __launch_bounds__(256) void gate_kernel(const float* __restrict__ fb)
{
    int id = blockIdx.x * blockDim.x + threadIdx.x;
    if (id >= MM * HH) return;
    int h = id % HH;
    int m = id / HH;
    size_t base = (size_t)m * GG;
    float f  = g_g[base + h];
    float iv = g_g[base + HH + h];
    float sp = log1pf(expf(fb[h]));
    float sf = 1.f / (1.f + expf(-f));
    float la = -8.f * sp * sf;
    float alpha = expf(la);
    float beta  = sqrtf(1.f - alpha * alpha + 1e-6f);
    float si = 1.f / (1.f + expf(-iv));
    float xs = beta * si * g_xc[id];
    g_g[base + h]      = alpha;
    g_g[base + HH + h] = xs;
}

// ---------------- chunked scan ----------------
__global__ __launch_bounds__(256) void scan1_kernel()
{
    int id = blockIdx.x * blockDim.x + threadIdx.x;
    if (id >= NB * NCHUNK * HH) return;
    int h = id % HH;
    int r = id / HH;
    int c = r % NCHUNK;
    int n = r / NCHUNK;
    float arun = 1.f, hrun = 0.f;
    int t0 = c * CLEN;
    for (int tl = 0; tl < CLEN; tl++) {
        size_t m = (size_t)n * TT + t0 + tl;
        float a = g_g[m * GG + h];
        float x = g_g[m * GG + HH + h];
        hrun = a * hrun + x;
        arun *= a;
        g_h[m * HH + h]    = hrun;
        g_cumA[m * HH + h] = arun;
    }
    g_carryA[id] = arun;
    g_carryH[id] = hrun;
}
__global__ __launch_bounds__(256) void scan2_kernel()
{
    int id = blockIdx.x * blockDim.x + threadIdx.x;
    if (id >= NB * HH) return;
    int h = id % HH;
    int n = id / HH;
    float hin = 0.f;
    for (int c = 0; c < NCHUNK; c++) {
        int j = (n * NCHUNK + c) * HH + h;
        g_chunkIn[j] = hin;
        hin = g_carryA[j] * hin + g_carryH[j];
    }
}

// ---------------- fixup + gelu(gate)*h, fused with split ----------------
__global__ __launch_bounds__(256) void mul_kernel()
{
    int id = blockIdx.x * blockDim.x + threadIdx.x;
    if (id >= MM * HH) return;
    int h = id % HH;
    int m = id / HH;
    int t = m % TT;
    int n = m / TT;
    int c = t / CLEN;
    float hv = g_h[id] + g_cumA[id] * g_chunkIn[(n * NCHUNK + c) * HH + h];
    float gate = g_u[(size_t)m * GG + h];
    float ge = 0.5f * gate * (1.f + erff(gate * 0.70710678118654752f));
    float v = ge * hv;
    __nv_bfloat16 hi, lo;
    split1(v, hi, lo);
    g_ahi[id] = hi;
    g_alo[id] = lo;
}

// ---------------- launch ----------------
extern "C" void kernel_launch(void* const* d_in, const int* in_sizes, int n_in,
                              void* d_out, int out_size)
{
    const float* x          = (const float*)d_in[0];
    const float* W_in       = (const float*)d_in[1];
    const float* conv_w     = (const float*)d_in[2];
    const float* conv_b     = (const float*)d_in[3];
    const float* W_gates    = (const float*)d_in[4];
    const float* b_gates    = (const float*)d_in[5];
    const float* forget_b   = (const float*)d_in[6];
    const float* W_out      = (const float*)d_in[7];
    float* out = (float*)d_out;

    // 1) split x and W_in to bf16 hi/lo
    split_x<<<(MM * DD / 4 + 255) / 256, 256>>>(x, MM * DD / 4);
    split_w<<<(GG * DD / 4 + 255) / 256, 256>>>(W_in, GG * DD / 4);
    // 2) u = x @ W_in^T  (tensor cores, 3-term split)
    {
        dim3 grid(GG / 128, MM / 128);
        tcgemm_in<<<grid, 256>>>();
    }
    // 3) causal conv (writes fp32 xc + bf16 hi/lo into A buffers)
    conv_kernel<<<(MM * HH) / 256, 256>>>(conv_w, conv_b);
    split_w<<<(GG * HH / 4 + 255) / 256, 256>>>(W_gates, GG * HH / 4);
    // 4) g = xc @ W_gates^T + b_gates
    {
        dim3 grid(GG / 128, MM / 128);
        tcgemm_gates<<<grid, 256>>>(b_gates);
    }
    // 5) gating -> alpha, xs
    gate_kernel<<<(MM * HH) / 256, 256>>>(forget_b);
    // 6) chunked linear scan
    scan1_kernel<<<(NB * NCHUNK * HH) / 256, 256>>>();
    scan2_kernel<<<(NB * HH + 255) / 256, 256>>>();
    // 7) fixup + gelu(gate)*h  (writes bf16 hi/lo into A buffers)
    mul_kernel<<<(MM * HH) / 256, 256>>>();
    split_w<<<(DD * HH / 4 + 255) / 256, 256>>>(W_out, DD * HH / 4);
    // 8) out = ga @ W_out^T
    {
        dim3 grid(DD / 128, MM / 128);
        tcgemm_out<<<grid, 256>>>(out);
    }
}